// round 1
// baseline (speedup 1.0000x reference)
#include <cuda_runtime.h>

#define BATCH 512
#define HO 31
#define WO 31
#define HW 64

// 6 coefficients per kernel (4 kernels): [ex_D, ex_d, ey_D, ey_d, ez_D, ez_d]
__device__ float g_coef[24];

__global__ void coef_kernel(const float* __restrict__ w) {
    int k = threadIdx.x;
    if (k < 4) {
        // weights layout (4,4,3): qubit 0 of kernel k -> w[k*12 + {0,1,2}]
        double th = (double)w[k * 12 + 0];
        double ph = (double)w[k * 12 + 1];
        double om = (double)w[k * 12 + 2];
        double st = sin(th), ct = cos(th);
        double c2 = 0.5 * (1.0 + ct);   // cos^2(theta/2)
        double s2 = 0.5 * (1.0 - ct);   // sin^2(theta/2)
        g_coef[k * 6 + 0] = (float)(st * cos(ph));
        g_coef[k * 6 + 1] = (float)(2.0 * (c2 * cos(ph + om) - s2 * cos(om - ph)));
        g_coef[k * 6 + 2] = (float)(st * sin(ph));
        g_coef[k * 6 + 3] = (float)(2.0 * (c2 * sin(ph + om) + s2 * sin(om - ph)));
        g_coef[k * 6 + 4] = (float)ct;
        g_coef[k * 6 + 5] = (float)(-2.0 * st * cos(om));
    }
}

__global__ __launch_bounds__(256) void qconv_kernel(const float* __restrict__ x,
                                                    float* __restrict__ out) {
    int wo = threadIdx.x;                     // 0..31 (31 active)
    int ho = blockIdx.y * 8 + threadIdx.y;    // blockDim.y = 8
    int b  = blockIdx.z;
    if (wo >= WO || ho >= HO) return;

    const float* base = x + (size_t)b * (HW * HW) + (ho * 2) * HW + wo * 2;

    // patch p[kh*4 + kw] = x[b, 0, 2*ho+kh, 2*wo+kw]
    float p[16];
#pragma unroll
    for (int r = 0; r < 4; ++r) {
        float2 u = *reinterpret_cast<const float2*>(base + r * HW);
        float2 v = *reinterpret_cast<const float2*>(base + r * HW + 2);
        p[4 * r + 0] = u.x;
        p[4 * r + 1] = u.y;
        p[4 * r + 2] = v.x;
        p[4 * r + 3] = v.y;
    }

    // Closed-form invariants of the circuit:
    //   S2 = sum p_i^2 ; D2 = signed sum (which MSB-half the ring-perm lands in)
    //   dP = sum over the 8 pairs (i, i^12) of p_i * p_{i^12}
    const float sgn[16] = {1.f, -1.f, -1.f, 1.f, -1.f, 1.f, 1.f, -1.f,
                           1.f, -1.f, -1.f, 1.f, -1.f, 1.f, 1.f, -1.f};
    float S2 = 0.f, D2 = 0.f, dP = 0.f;
#pragma unroll
    for (int i = 0; i < 16; ++i) {
        float q = p[i] * p[i];
        S2 += q;
        D2 += sgn[i] * q;
    }
#pragma unroll
    for (int j = 0; j < 8; ++j) dP += p[j] * p[j ^ 12];

    float inv = 1.0f / S2;       // eps in the reference cancels exactly
    float Dl = D2 * inv;         // <n0 - n1> before wire-0 gate
    float dd = dP * inv;         // q0 . q1

    size_t obase = (size_t)b * 12 * (HO * WO) + ho * WO + wo;
#pragma unroll
    for (int k = 0; k < 4; ++k) {
        float c0 = g_coef[k * 6 + 0];
        float c1 = g_coef[k * 6 + 1];
        float c2 = g_coef[k * 6 + 2];
        float c3 = g_coef[k * 6 + 3];
        float c4 = g_coef[k * 6 + 4];
        float c5 = g_coef[k * 6 + 5];
        out[obase + (size_t)(3 * k + 0) * (HO * WO)] = c0 * Dl + c1 * dd;
        out[obase + (size_t)(3 * k + 1) * (HO * WO)] = c2 * Dl + c3 * dd;
        out[obase + (size_t)(3 * k + 2) * (HO * WO)] = c4 * Dl + c5 * dd;
    }
}

extern "C" void kernel_launch(void* const* d_in, const int* in_sizes, int n_in,
                              void* d_out, int out_size) {
    const float* x = (const float*)d_in[0];
    const float* w = (const float*)d_in[1];
    if (n_in >= 2 && in_sizes[0] == 48) {  // robustness: weights listed first
        x = (const float*)d_in[1];
        w = (const float*)d_in[0];
    }
    float* out = (float*)d_out;

    coef_kernel<<<1, 4>>>(w);

    dim3 blk(32, 8, 1);
    dim3 grd(1, (HO + 7) / 8, BATCH);
    qconv_kernel<<<grd, blk>>>(x, out);
}

// round 2
// speedup vs baseline: 1.4742x; 1.4742x over previous
#include <cuda_runtime.h>
#include <math.h>

#define BATCH 512
#define HO 31
#define WO 31
#define HW 64
#define PLANE (HO * WO)

// Per-patch closed-form invariants of the quantum circuit:
//   S2 = sum p_i^2 (normalization)
//   D2 = signed sum of p_i^2 (which MSB-half the CNOT-ring permutation maps i to)
//   dP = sum over pairs (i, i^12): rows 0<->3 and 1<->2, same column
// Outputs are a per-kernel 3x2 linear map of (D2/S2, dP/S2) with coefficients
// depending only on U3(theta,phi,omega) of qubit 0 (the wires-1..3 unitary
// cancels because the input state is real and only wire 0 is measured).

__global__ __launch_bounds__(256) void qconv_kernel(const float* __restrict__ x,
                                                    const float* __restrict__ w,
                                                    float* __restrict__ out) {
    __shared__ float cf[24];
    const int tid = threadIdx.y * 16 + threadIdx.x;
    if (tid < 4) {
        const int k = tid;
        float th = w[k * 12 + 0], ph = w[k * 12 + 1], om = w[k * 12 + 2];
        float st, ct, spo, cpo, smp, cmp, sp, cp, som, com_;
        sincosf(th, &st, &ct);
        sincosf(ph, &sp, &cp);
        sincosf(ph + om, &spo, &cpo);
        sincosf(om - ph, &smp, &cmp);
        sincosf(om, &som, &com_);
        float c2 = 0.5f * (1.0f + ct);  // cos^2(theta/2)
        float s2 = 0.5f * (1.0f - ct);  // sin^2(theta/2)
        cf[k * 6 + 0] = st * cp;
        cf[k * 6 + 1] = 2.0f * (c2 * cpo - s2 * cmp);
        cf[k * 6 + 2] = st * sp;
        cf[k * 6 + 3] = 2.0f * (c2 * spo + s2 * smp);
        cf[k * 6 + 4] = ct;
        cf[k * 6 + 5] = -2.0f * st * com_;
    }
    __syncthreads();

    const int t = threadIdx.x;                       // 0..15 -> wo pair (2t, 2t+1)
    const int ho = blockIdx.y * 16 + threadIdx.y;
    const int b = blockIdx.z;
    if (ho >= HO) return;

    const float* base = x + (size_t)b * (HW * HW) + (ho * 2) * HW + t * 4;
    const bool two = (t < 15);                       // wo=2t+1 exists (WO=31 odd)

    float4 A[4];
    float2 Bv[4];
#pragma unroll
    for (int r = 0; r < 4; ++r)
        A[r] = *reinterpret_cast<const float4*>(base + r * HW);
    if (two) {
#pragma unroll
        for (int r = 0; r < 4; ++r)
            Bv[r] = *reinterpret_cast<const float2*>(base + r * HW + 4);
    }

    // ---- patch 0: columns (A.x, A.y, A.z, A.w) ----
    float S0 = 0.f, D0 = 0.f;
#pragma unroll
    for (int r = 0; r < 4; ++r) {
        float xx = A[r].x * A[r].x, yy = A[r].y * A[r].y;
        float zz = A[r].z * A[r].z, ww = A[r].w * A[r].w;
        S0 += xx + yy + zz + ww;
        float d = xx - yy - zz + ww;
        D0 += (r & 1) ? -d : d;
    }
    float P0 = A[0].x * A[3].x + A[0].y * A[3].y + A[0].z * A[3].z + A[0].w * A[3].w
             + A[1].x * A[2].x + A[1].y * A[2].y + A[1].z * A[2].z + A[1].w * A[2].w;

    const size_t obase = (size_t)b * 12 * PLANE + ho * WO + 2 * t;
    {
        float inv = 1.0f / S0;
        float Dl = D0 * inv, dd = P0 * inv;
#pragma unroll
        for (int k = 0; k < 4; ++k) {
            out[obase + (size_t)(3 * k + 0) * PLANE] = cf[k * 6 + 0] * Dl + cf[k * 6 + 1] * dd;
            out[obase + (size_t)(3 * k + 1) * PLANE] = cf[k * 6 + 2] * Dl + cf[k * 6 + 3] * dd;
            out[obase + (size_t)(3 * k + 2) * PLANE] = cf[k * 6 + 4] * Dl + cf[k * 6 + 5] * dd;
        }
    }

    // ---- patch 1: columns (A.z, A.w, B.x, B.y) ----
    if (two) {
        float S1 = 0.f, D1 = 0.f;
#pragma unroll
        for (int r = 0; r < 4; ++r) {
            float xx = A[r].z * A[r].z, yy = A[r].w * A[r].w;
            float zz = Bv[r].x * Bv[r].x, ww = Bv[r].y * Bv[r].y;
            S1 += xx + yy + zz + ww;
            float d = xx - yy - zz + ww;
            D1 += (r & 1) ? -d : d;
        }
        float P1 = A[0].z * A[3].z + A[0].w * A[3].w + Bv[0].x * Bv[3].x + Bv[0].y * Bv[3].y
                 + A[1].z * A[2].z + A[1].w * A[2].w + Bv[1].x * Bv[2].x + Bv[1].y * Bv[2].y;

        float inv = 1.0f / S1;
        float Dl = D1 * inv, dd = P1 * inv;
#pragma unroll
        for (int k = 0; k < 4; ++k) {
            out[obase + 1 + (size_t)(3 * k + 0) * PLANE] = cf[k * 6 + 0] * Dl + cf[k * 6 + 1] * dd;
            out[obase + 1 + (size_t)(3 * k + 1) * PLANE] = cf[k * 6 + 2] * Dl + cf[k * 6 + 3] * dd;
            out[obase + 1 + (size_t)(3 * k + 2) * PLANE] = cf[k * 6 + 4] * Dl + cf[k * 6 + 5] * dd;
        }
    }
}

extern "C" void kernel_launch(void* const* d_in, const int* in_sizes, int n_in,
                              void* d_out, int out_size) {
    const float* x = (const float*)d_in[0];
    const float* w = (const float*)d_in[1];
    if (n_in >= 2 && in_sizes[0] == 48) {  // robustness: weights listed first
        x = (const float*)d_in[1];
        w = (const float*)d_in[0];
    }
    float* out = (float*)d_out;

    dim3 blk(16, 16, 1);
    dim3 grd(1, (HO + 15) / 16, BATCH);
    qconv_kernel<<<grd, blk>>>(x, w, out);
}

// round 3
// speedup vs baseline: 1.7857x; 1.2113x over previous
#include <cuda_runtime.h>
#include <math.h>

#define BATCH 512
#define HO 31
#define WO 31
#define HW 64
#define PLANE (HO * WO)

// Per-patch closed-form invariants of the quantum circuit:
//   S2 = sum p_i^2 (normalization)
//   D2 = signed sum of p_i^2 (which MSB-half the CNOT-ring permutation maps i to)
//   dP = sum over pairs (i, i^12): rows 0<->3 and 1<->2, same column
// Outputs are a per-kernel 3x2 linear map of (D2/S2, dP/S2) with coefficients
// depending only on U3(theta,phi,omega) of qubit 0 (the wires-1..3 unitary
// cancels because the input state is real and only wire 0 is measured).

__global__ __launch_bounds__(256) void qconv_kernel(const float* __restrict__ x,
                                                    const float* __restrict__ w,
                                                    float* __restrict__ out) {
    __shared__ float cf[24];
    const int tid = threadIdx.y * 32 + threadIdx.x;
    if (tid < 4) {
        const int k = tid;
        float th = w[k * 12 + 0], ph = w[k * 12 + 1], om = w[k * 12 + 2];
        float st, ct, spo, cpo, smp, cmp, sp, cp, som, com_;
        sincosf(th, &st, &ct);
        sincosf(ph, &sp, &cp);
        sincosf(ph + om, &spo, &cpo);
        sincosf(om - ph, &smp, &cmp);
        sincosf(om, &som, &com_);
        float c2 = 0.5f * (1.0f + ct);  // cos^2(theta/2)
        float s2 = 0.5f * (1.0f - ct);  // sin^2(theta/2)
        cf[k * 6 + 0] = st * cp;
        cf[k * 6 + 1] = 2.0f * (c2 * cpo - s2 * cmp);
        cf[k * 6 + 2] = st * sp;
        cf[k * 6 + 3] = 2.0f * (c2 * spo + s2 * smp);
        cf[k * 6 + 4] = ct;
        cf[k * 6 + 5] = -2.0f * st * com_;
    }
    __syncthreads();

    const int wo = threadIdx.x;                    // 0..31 (31 active)
    const int ho = blockIdx.y * 8 + threadIdx.y;   // blockDim.y = 8
    const int b  = blockIdx.z;
    if (wo >= WO || ho >= HO) return;

    const float* base = x + (size_t)b * (HW * HW) + (ho * 2) * HW + wo * 2;

    // patch p[kh*4 + kw] = x[b, 0, 2*ho+kh, 2*wo+kw]
    float p[16];
#pragma unroll
    for (int r = 0; r < 4; ++r) {
        float2 u = *reinterpret_cast<const float2*>(base + r * HW);
        float2 v = *reinterpret_cast<const float2*>(base + r * HW + 2);
        p[4 * r + 0] = u.x;
        p[4 * r + 1] = u.y;
        p[4 * r + 2] = v.x;
        p[4 * r + 3] = v.y;
    }

    const float sgn[16] = {1.f, -1.f, -1.f, 1.f, -1.f, 1.f, 1.f, -1.f,
                           1.f, -1.f, -1.f, 1.f, -1.f, 1.f, 1.f, -1.f};
    float S2 = 0.f, D2 = 0.f, dP = 0.f;
#pragma unroll
    for (int i = 0; i < 16; ++i) {
        float q = p[i] * p[i];
        S2 += q;
        D2 += sgn[i] * q;
    }
#pragma unroll
    for (int j = 0; j < 8; ++j) dP += p[j] * p[j ^ 12];

    float inv = 1.0f / S2;       // eps in the reference cancels exactly
    float Dl = D2 * inv;
    float dd = dP * inv;

    size_t obase = (size_t)b * 12 * PLANE + ho * WO + wo;
#pragma unroll
    for (int k = 0; k < 4; ++k) {
        float c0 = cf[k * 6 + 0];
        float c1 = cf[k * 6 + 1];
        float c2 = cf[k * 6 + 2];
        float c3 = cf[k * 6 + 3];
        float c4 = cf[k * 6 + 4];
        float c5 = cf[k * 6 + 5];
        out[obase + (size_t)(3 * k + 0) * PLANE] = c0 * Dl + c1 * dd;
        out[obase + (size_t)(3 * k + 1) * PLANE] = c2 * Dl + c3 * dd;
        out[obase + (size_t)(3 * k + 2) * PLANE] = c4 * Dl + c5 * dd;
    }
}

extern "C" void kernel_launch(void* const* d_in, const int* in_sizes, int n_in,
                              void* d_out, int out_size) {
    const float* x = (const float*)d_in[0];
    const float* w = (const float*)d_in[1];
    if (n_in >= 2 && in_sizes[0] == 48) {  // robustness: weights listed first
        x = (const float*)d_in[1];
        w = (const float*)d_in[0];
    }
    float* out = (float*)d_out;

    dim3 blk(32, 8, 1);
    dim3 grd(1, (HO + 7) / 8, BATCH);
    qconv_kernel<<<grd, blk>>>(x, w, out);
}